// round 4
// baseline (speedup 1.0000x reference)
#include <cuda_runtime.h>

#define Nn 100000
#define Ff 64
#define Ee 1600000

// Scratch (device globals — no allocation allowed anywhere)
__device__ float g_deg[Nn];
__device__ float g_dinv[Nn];
__device__ int   g_cnt[Nn];
__device__ int   g_off[Nn];
__device__ int   g_cursor[Nn];
__device__ int   g_csr_row[Ee];
__device__ float g_csr_nw[Ee];
__device__ float g_h0[(size_t)Nn * Ff];
__device__ float g_agg[(size_t)Nn * Ff];
__device__ float g_out1[(size_t)Nn * Ff];

// ---------------------------------------------------------------------------
// Zero deg + cnt
// ---------------------------------------------------------------------------
__global__ void zero_kernel() {
    int i = blockIdx.x * blockDim.x + threadIdx.x;
    if (i < Nn) { g_deg[i] = 0.f; g_cnt[i] = 0; }
}

// ---------------------------------------------------------------------------
// deg[col[e]] += w[e];  cnt[col[e]] += 1   (scalar atomics only)
// edge_index arrives as int32 (harness converts int64 -> int32).
// ---------------------------------------------------------------------------
__global__ void deg_kernel(const int* __restrict__ cols,
                           const float* __restrict__ ew) {
    int e = blockIdx.x * blockDim.x + threadIdx.x;
    if (e < Ee) {
        unsigned c = (unsigned)cols[e];
        if (c < Nn) {
            atomicAdd(&g_deg[c], ew[e]);
            atomicAdd(&g_cnt[c], 1);
        }
    }
}

__global__ void dinv_kernel() {
    int i = blockIdx.x * blockDim.x + threadIdx.x;
    if (i < Nn) {
        float d = g_deg[i];
        g_dinv[i] = d > 0.f ? rsqrtf(d) : 0.f;
    }
}

// ---------------------------------------------------------------------------
// Exclusive prefix scan of g_cnt -> g_off, g_cursor. One block, 1024 threads.
// ---------------------------------------------------------------------------
__global__ void __launch_bounds__(1024)
scan_kernel() {
    __shared__ int sm[1024];
    const int CH = (Nn + 1023) / 1024;  // 98
    int t = threadIdx.x;
    int lo = t * CH;
    int hi = lo + CH; if (hi > Nn) hi = Nn;
    int s = 0;
    for (int i = lo; i < hi; i++) s += g_cnt[i];
    sm[t] = s;
    __syncthreads();
    // Hillis-Steele inclusive scan
    for (int d = 1; d < 1024; d <<= 1) {
        int v = (t >= d) ? sm[t - d] : 0;
        __syncthreads();
        sm[t] += v;
        __syncthreads();
    }
    int run = (t > 0) ? sm[t - 1] : 0;  // exclusive base
    for (int i = lo; i < hi; i++) {
        g_off[i] = run;
        g_cursor[i] = run;
        run += g_cnt[i];
    }
}

// ---------------------------------------------------------------------------
// Scatter edges into CSR slots: csr_row / csr_nw grouped by col.
// ---------------------------------------------------------------------------
__global__ void scatter_kernel(const int* __restrict__ rows,
                               const int* __restrict__ cols,
                               const float* __restrict__ ew) {
    int e = blockIdx.x * blockDim.x + threadIdx.x;
    if (e < Ee) {
        unsigned r = (unsigned)rows[e];
        unsigned c = (unsigned)cols[e];
        if (r < Nn && c < Nn) {
            int p = atomicAdd(&g_cursor[c], 1);
            g_csr_row[p] = r;
            g_csr_nw[p] = g_dinv[r] * ew[e] * g_dinv[c];
        }
    }
}

// ---------------------------------------------------------------------------
// SpMM gather: agg[n] = sum_{edges into n} nw * h[row].  One warp per node,
// each lane owns 2 feature floats. No float atomics.
// ---------------------------------------------------------------------------
__global__ void __launch_bounds__(256)
gather_kernel(int src) {
    int w = (blockIdx.x * 256 + threadIdx.x) >> 5;   // node id
    int lane = threadIdx.x & 31;
    if (w >= Nn) return;
    const float* __restrict__ h = src ? g_out1 : g_h0;
    int beg = g_off[w];
    int end = beg + g_cnt[w];
    float2 acc = make_float2(0.f, 0.f);
    for (int j = beg; j < end; j++) {
        int r = g_csr_row[j];          // broadcast across warp
        float nw = g_csr_nw[j];
        float2 v = *(const float2*)(h + (size_t)r * Ff + lane * 2);
        acc.x = fmaf(nw, v.x, acc.x);
        acc.y = fmaf(nw, v.y, acc.y);
    }
    *(float2*)(g_agg + (size_t)w * Ff + lane * 2) = acc;
}

// ---------------------------------------------------------------------------
// GEMM h0 = relu(x @ W0^T + b).  Block tile: 128 nodes x 64 feats, 256 thr.
// ---------------------------------------------------------------------------
__global__ void __launch_bounds__(256)
gemm_h0_kernel(const float* __restrict__ x, const float* __restrict__ w0,
               const float* __restrict__ b) {
    __shared__ __align__(16) float As[64][128];  // [k][node]
    __shared__ __align__(16) float Ws[64][64];   // [k][f]
    int t = threadIdx.x;
    int n0 = blockIdx.x * 128;

    for (int i = t; i < 4096; i += 256) {
        int k = i >> 6, f = i & 63;
        Ws[k][f] = w0[f * 64 + k];  // transpose: need W0[f][k] at [k][f]
    }
    for (int i = t * 4; i < 8192; i += 1024) {
        int node = i >> 6, k = i & 63;
        int gn = n0 + node;
        float4 v = make_float4(0.f, 0.f, 0.f, 0.f);
        if (gn < Nn) v = *(const float4*)(x + (size_t)gn * 64 + k);
        As[k + 0][node] = v.x; As[k + 1][node] = v.y;
        As[k + 2][node] = v.z; As[k + 3][node] = v.w;
    }
    __syncthreads();

    int tf = (t & 15) * 4;
    int tn = (t >> 4) * 8;
    float acc[8][4];
#pragma unroll
    for (int j = 0; j < 8; j++)
        acc[j][0] = acc[j][1] = acc[j][2] = acc[j][3] = 0.f;

#pragma unroll 8
    for (int k = 0; k < 64; k++) {
        float4 w4 = *(const float4*)&Ws[k][tf];
        float4 a0 = *(const float4*)&As[k][tn];
        float4 a1 = *(const float4*)&As[k][tn + 4];
        float a[8] = {a0.x, a0.y, a0.z, a0.w, a1.x, a1.y, a1.z, a1.w};
#pragma unroll
        for (int j = 0; j < 8; j++) {
            acc[j][0] = fmaf(a[j], w4.x, acc[j][0]);
            acc[j][1] = fmaf(a[j], w4.y, acc[j][1]);
            acc[j][2] = fmaf(a[j], w4.z, acc[j][2]);
            acc[j][3] = fmaf(a[j], w4.w, acc[j][3]);
        }
    }
    float4 bv = *(const float4*)(b + tf);
#pragma unroll
    for (int j = 0; j < 8; j++) {
        int gn = n0 + tn + j;
        if (gn < Nn) {
            float4 r;
            r.x = fmaxf(acc[j][0] + bv.x, 0.f);
            r.y = fmaxf(acc[j][1] + bv.y, 0.f);
            r.z = fmaxf(acc[j][2] + bv.z, 0.f);
            r.w = fmaxf(acc[j][3] + bv.w, 0.f);
            *(float4*)&g_h0[(size_t)gn * 64 + tf] = r;
        }
    }
}

// ---------------------------------------------------------------------------
// Fused conv GEMM: out = prev + relu( (0.1*agg + 0.9*h0) @ W1 )
// layer 0: prev = h0,   out = g_out1
// layer 1: prev = out1, out = d_out
// ---------------------------------------------------------------------------
__global__ void __launch_bounds__(256)
gemm_conv_kernel(const float* __restrict__ w1, int layer,
                 float* __restrict__ dout) {
    __shared__ __align__(16) float As[64][128];
    __shared__ __align__(16) float Ws[64][64];
    int t = threadIdx.x;
    int n0 = blockIdx.x * 128;
    const float* __restrict__ prev = layer ? g_out1 : g_h0;
    float* __restrict__ out = layer ? dout : g_out1;

    for (int i = t; i < 4096; i += 256) {
        Ws[i >> 6][i & 63] = w1[i];  // already [k][f]
    }
    for (int i = t * 4; i < 8192; i += 1024) {
        int node = i >> 6, k = i & 63;
        int gn = n0 + node;
        float4 v = make_float4(0.f, 0.f, 0.f, 0.f);
        if (gn < Nn) {
            float4 a = *(const float4*)(g_agg + (size_t)gn * 64 + k);
            float4 h = *(const float4*)(g_h0 + (size_t)gn * 64 + k);
            v.x = fmaf(0.1f, a.x, 0.9f * h.x);
            v.y = fmaf(0.1f, a.y, 0.9f * h.y);
            v.z = fmaf(0.1f, a.z, 0.9f * h.z);
            v.w = fmaf(0.1f, a.w, 0.9f * h.w);
        }
        As[k + 0][node] = v.x; As[k + 1][node] = v.y;
        As[k + 2][node] = v.z; As[k + 3][node] = v.w;
    }
    __syncthreads();

    int tf = (t & 15) * 4;
    int tn = (t >> 4) * 8;
    float acc[8][4];
#pragma unroll
    for (int j = 0; j < 8; j++)
        acc[j][0] = acc[j][1] = acc[j][2] = acc[j][3] = 0.f;

#pragma unroll 8
    for (int k = 0; k < 64; k++) {
        float4 w4 = *(const float4*)&Ws[k][tf];
        float4 a0 = *(const float4*)&As[k][tn];
        float4 a1 = *(const float4*)&As[k][tn + 4];
        float a[8] = {a0.x, a0.y, a0.z, a0.w, a1.x, a1.y, a1.z, a1.w};
#pragma unroll
        for (int j = 0; j < 8; j++) {
            acc[j][0] = fmaf(a[j], w4.x, acc[j][0]);
            acc[j][1] = fmaf(a[j], w4.y, acc[j][1]);
            acc[j][2] = fmaf(a[j], w4.z, acc[j][2]);
            acc[j][3] = fmaf(a[j], w4.w, acc[j][3]);
        }
    }
#pragma unroll
    for (int j = 0; j < 8; j++) {
        int gn = n0 + tn + j;
        if (gn < Nn) {
            float4 p = *(const float4*)(prev + (size_t)gn * 64 + tf);
            float4 r;
            r.x = p.x + fmaxf(acc[j][0], 0.f);
            r.y = p.y + fmaxf(acc[j][1], 0.f);
            r.z = p.z + fmaxf(acc[j][2], 0.f);
            r.w = p.w + fmaxf(acc[j][3], 0.f);
            *(float4*)(out + (size_t)gn * 64 + tf) = r;
        }
    }
}

// ---------------------------------------------------------------------------
extern "C" void kernel_launch(void* const* d_in, const int* in_sizes, int n_in,
                              void* d_out, int out_size) {
    const float* x  = (const float*)d_in[0];
    const int*   ei = (const int*)d_in[1];   // int32! (harness: int64 -> int32)
    const float* ew = (const float*)d_in[2];
    // d_in[3] = edge_attr (unused by the module)
    const float* w0 = (const float*)d_in[4];
    const float* b0 = (const float*)d_in[5];
    const float* w1 = (const float*)d_in[6];
    float* out = (float*)d_out;

    const int* rows = ei;
    const int* cols = ei + Ee;

    const int EB = (Ee + 255) / 256;
    const int NB = (Nn + 255) / 256;
    const int GB = (Nn + 127) / 128;       // gemm blocks (128 nodes/block)
    const int WB = (Nn + 7) / 8;           // gather blocks (8 warps = 8 nodes/block)

    zero_kernel<<<NB, 256>>>();
    deg_kernel<<<EB, 256>>>(cols, ew);
    dinv_kernel<<<NB, 256>>>();
    scan_kernel<<<1, 1024>>>();
    scatter_kernel<<<EB, 256>>>(rows, cols, ew);
    gemm_h0_kernel<<<GB, 256>>>(x, w0, b0);

    // layer 1
    gather_kernel<<<WB, 256>>>(0);
    gemm_conv_kernel<<<GB, 256>>>(w1, 0, out);

    // layer 2
    gather_kernel<<<WB, 256>>>(1);
    gemm_conv_kernel<<<GB, 256>>>(w1 + 64 * 64, 1, out);
}

// round 5
// speedup vs baseline: 1.5341x; 1.5341x over previous
#include <cuda_runtime.h>

#define Nn 100000
#define Ff 64
#define Ee 1600000
#define SCAN_B 98   // ceil(Nn/1024)

// Scratch (device globals — no allocation allowed anywhere)
__device__ float g_deg[Nn];
__device__ float g_dinv[Nn];
__device__ int   g_cnt[Nn];
__device__ int   g_off[Nn];
__device__ int   g_cursor[Nn];
__device__ int   g_bsum[128];
__device__ int   g_bbase[128];
__device__ int   g_csr_row[Ee];
__device__ float g_csr_nw[Ee];
__device__ float g_h0[(size_t)Nn * Ff];
__device__ float g_agg[(size_t)Nn * Ff];
__device__ float g_out1[(size_t)Nn * Ff];

// ---------------------------------------------------------------------------
// Zero deg + cnt
// ---------------------------------------------------------------------------
__global__ void zero_kernel() {
    int i = blockIdx.x * blockDim.x + threadIdx.x;
    if (i < Nn) { g_deg[i] = 0.f; g_cnt[i] = 0; }
}

// ---------------------------------------------------------------------------
// deg[col[e]] += w[e];  cnt[col[e]] += 1   (scalar atomics only)
// ---------------------------------------------------------------------------
__global__ void deg_kernel(const int* __restrict__ cols,
                           const float* __restrict__ ew) {
    int e = blockIdx.x * blockDim.x + threadIdx.x;
    if (e < Ee) {
        unsigned c = (unsigned)cols[e];
        if (c < Nn) {
            atomicAdd(&g_deg[c], ew[e]);
            atomicAdd(&g_cnt[c], 1);
        }
    }
}

__global__ void dinv_kernel() {
    int i = blockIdx.x * blockDim.x + threadIdx.x;
    if (i < Nn) {
        float d = g_deg[i];
        g_dinv[i] = d > 0.f ? rsqrtf(d) : 0.f;
    }
}

// ---------------------------------------------------------------------------
// 3-phase exclusive scan of g_cnt -> g_off/g_cursor (multi-block, full chip)
// ---------------------------------------------------------------------------
__global__ void __launch_bounds__(1024)
scan_sum_kernel() {
    __shared__ int sm[1024];
    int t = threadIdx.x;
    int i = blockIdx.x * 1024 + t;
    sm[t] = (i < Nn) ? g_cnt[i] : 0;
    __syncthreads();
    for (int d = 512; d > 0; d >>= 1) {
        if (t < d) sm[t] += sm[t + d];
        __syncthreads();
    }
    if (t == 0) g_bsum[blockIdx.x] = sm[0];
}

__global__ void __launch_bounds__(128)
scan_base_kernel() {
    __shared__ int sm[128];
    int t = threadIdx.x;
    int v = (t < SCAN_B) ? g_bsum[t] : 0;
    sm[t] = v;
    __syncthreads();
    for (int d = 1; d < 128; d <<= 1) {
        int u = (t >= d) ? sm[t - d] : 0;
        __syncthreads();
        sm[t] += u;
        __syncthreads();
    }
    if (t < SCAN_B) g_bbase[t] = sm[t] - v;  // exclusive
}

__global__ void __launch_bounds__(1024)
scan_final_kernel() {
    __shared__ int sm[1024];
    int t = threadIdx.x;
    int i = blockIdx.x * 1024 + t;
    int v = (i < Nn) ? g_cnt[i] : 0;
    sm[t] = v;
    __syncthreads();
    for (int d = 1; d < 1024; d <<= 1) {
        int u = (t >= d) ? sm[t - d] : 0;
        __syncthreads();
        sm[t] += u;
        __syncthreads();
    }
    if (i < Nn) {
        int off = g_bbase[blockIdx.x] + sm[t] - v;  // exclusive + base
        g_off[i] = off;
        g_cursor[i] = off;
    }
}

// ---------------------------------------------------------------------------
// Scatter edges into CSR slots: csr_row / csr_nw grouped by col.
// ---------------------------------------------------------------------------
__global__ void scatter_kernel(const int* __restrict__ rows,
                               const int* __restrict__ cols,
                               const float* __restrict__ ew) {
    int e = blockIdx.x * blockDim.x + threadIdx.x;
    if (e < Ee) {
        unsigned r = (unsigned)rows[e];
        unsigned c = (unsigned)cols[e];
        if (r < Nn && c < Nn) {
            int p = atomicAdd(&g_cursor[c], 1);
            g_csr_row[p] = r;
            g_csr_nw[p] = g_dinv[r] * ew[e] * g_dinv[c];
        }
    }
}

// ---------------------------------------------------------------------------
// SpMM gather: agg[n] = sum_{edges into n} nw * h[row].  One warp per node,
// each lane owns 2 feature floats. Two independent edge streams for MLP.
// ---------------------------------------------------------------------------
__global__ void __launch_bounds__(256)
gather_kernel(int src) {
    int w = (blockIdx.x * 256 + threadIdx.x) >> 5;   // node id
    int lane = threadIdx.x & 31;
    if (w >= Nn) return;
    const float* __restrict__ h = src ? g_out1 : g_h0;
    int beg = g_off[w];
    int end = beg + g_cnt[w];
    float2 acc0 = make_float2(0.f, 0.f);
    float2 acc1 = make_float2(0.f, 0.f);
    int j = beg;
    for (; j + 2 <= end; j += 2) {
        int r0 = g_csr_row[j];
        int r1 = g_csr_row[j + 1];
        float nw0 = g_csr_nw[j];
        float nw1 = g_csr_nw[j + 1];
        float2 v0 = *(const float2*)(h + (size_t)r0 * Ff + lane * 2);
        float2 v1 = *(const float2*)(h + (size_t)r1 * Ff + lane * 2);
        acc0.x = fmaf(nw0, v0.x, acc0.x);
        acc0.y = fmaf(nw0, v0.y, acc0.y);
        acc1.x = fmaf(nw1, v1.x, acc1.x);
        acc1.y = fmaf(nw1, v1.y, acc1.y);
    }
    if (j < end) {
        int r0 = g_csr_row[j];
        float nw0 = g_csr_nw[j];
        float2 v0 = *(const float2*)(h + (size_t)r0 * Ff + lane * 2);
        acc0.x = fmaf(nw0, v0.x, acc0.x);
        acc0.y = fmaf(nw0, v0.y, acc0.y);
    }
    acc0.x += acc1.x;
    acc0.y += acc1.y;
    *(float2*)(g_agg + (size_t)w * Ff + lane * 2) = acc0;
}

// ---------------------------------------------------------------------------
// GEMM h0 = relu(x @ W0^T + b).  Block tile: 128 nodes x 64 feats, 256 thr.
// ---------------------------------------------------------------------------
__global__ void __launch_bounds__(256)
gemm_h0_kernel(const float* __restrict__ x, const float* __restrict__ w0,
               const float* __restrict__ b) {
    __shared__ __align__(16) float As[64][128];  // [k][node]
    __shared__ __align__(16) float Ws[64][64];   // [k][f]
    int t = threadIdx.x;
    int n0 = blockIdx.x * 128;

    for (int i = t; i < 4096; i += 256) {
        int k = i >> 6, f = i & 63;
        Ws[k][f] = w0[f * 64 + k];  // transpose: need W0[f][k] at [k][f]
    }
    for (int i = t * 4; i < 8192; i += 1024) {
        int node = i >> 6, k = i & 63;
        int gn = n0 + node;
        float4 v = make_float4(0.f, 0.f, 0.f, 0.f);
        if (gn < Nn) v = *(const float4*)(x + (size_t)gn * 64 + k);
        As[k + 0][node] = v.x; As[k + 1][node] = v.y;
        As[k + 2][node] = v.z; As[k + 3][node] = v.w;
    }
    __syncthreads();

    int tf = (t & 15) * 4;
    int tn = (t >> 4) * 8;
    float acc[8][4];
#pragma unroll
    for (int j = 0; j < 8; j++)
        acc[j][0] = acc[j][1] = acc[j][2] = acc[j][3] = 0.f;

#pragma unroll 8
    for (int k = 0; k < 64; k++) {
        float4 w4 = *(const float4*)&Ws[k][tf];
        float4 a0 = *(const float4*)&As[k][tn];
        float4 a1 = *(const float4*)&As[k][tn + 4];
        float a[8] = {a0.x, a0.y, a0.z, a0.w, a1.x, a1.y, a1.z, a1.w};
#pragma unroll
        for (int j = 0; j < 8; j++) {
            acc[j][0] = fmaf(a[j], w4.x, acc[j][0]);
            acc[j][1] = fmaf(a[j], w4.y, acc[j][1]);
            acc[j][2] = fmaf(a[j], w4.z, acc[j][2]);
            acc[j][3] = fmaf(a[j], w4.w, acc[j][3]);
        }
    }
    float4 bv = *(const float4*)(b + tf);
#pragma unroll
    for (int j = 0; j < 8; j++) {
        int gn = n0 + tn + j;
        if (gn < Nn) {
            float4 r;
            r.x = fmaxf(acc[j][0] + bv.x, 0.f);
            r.y = fmaxf(acc[j][1] + bv.y, 0.f);
            r.z = fmaxf(acc[j][2] + bv.z, 0.f);
            r.w = fmaxf(acc[j][3] + bv.w, 0.f);
            *(float4*)&g_h0[(size_t)gn * 64 + tf] = r;
        }
    }
}

// ---------------------------------------------------------------------------
// Fused conv GEMM: out = prev + relu( (0.1*agg + 0.9*h0) @ W1 )
// layer 0: prev = h0,   out = g_out1
// layer 1: prev = out1, out = d_out
// ---------------------------------------------------------------------------
__global__ void __launch_bounds__(256)
gemm_conv_kernel(const float* __restrict__ w1, int layer,
                 float* __restrict__ dout) {
    __shared__ __align__(16) float As[64][128];
    __shared__ __align__(16) float Ws[64][64];
    int t = threadIdx.x;
    int n0 = blockIdx.x * 128;
    const float* __restrict__ prev = layer ? g_out1 : g_h0;
    float* __restrict__ out = layer ? dout : g_out1;

    for (int i = t; i < 4096; i += 256) {
        Ws[i >> 6][i & 63] = w1[i];  // already [k][f]
    }
    for (int i = t * 4; i < 8192; i += 1024) {
        int node = i >> 6, k = i & 63;
        int gn = n0 + node;
        float4 v = make_float4(0.f, 0.f, 0.f, 0.f);
        if (gn < Nn) {
            float4 a = *(const float4*)(g_agg + (size_t)gn * 64 + k);
            float4 h = *(const float4*)(g_h0 + (size_t)gn * 64 + k);
            v.x = fmaf(0.1f, a.x, 0.9f * h.x);
            v.y = fmaf(0.1f, a.y, 0.9f * h.y);
            v.z = fmaf(0.1f, a.z, 0.9f * h.z);
            v.w = fmaf(0.1f, a.w, 0.9f * h.w);
        }
        As[k + 0][node] = v.x; As[k + 1][node] = v.y;
        As[k + 2][node] = v.z; As[k + 3][node] = v.w;
    }
    __syncthreads();

    int tf = (t & 15) * 4;
    int tn = (t >> 4) * 8;
    float acc[8][4];
#pragma unroll
    for (int j = 0; j < 8; j++)
        acc[j][0] = acc[j][1] = acc[j][2] = acc[j][3] = 0.f;

#pragma unroll 8
    for (int k = 0; k < 64; k++) {
        float4 w4 = *(const float4*)&Ws[k][tf];
        float4 a0 = *(const float4*)&As[k][tn];
        float4 a1 = *(const float4*)&As[k][tn + 4];
        float a[8] = {a0.x, a0.y, a0.z, a0.w, a1.x, a1.y, a1.z, a1.w};
#pragma unroll
        for (int j = 0; j < 8; j++) {
            acc[j][0] = fmaf(a[j], w4.x, acc[j][0]);
            acc[j][1] = fmaf(a[j], w4.y, acc[j][1]);
            acc[j][2] = fmaf(a[j], w4.z, acc[j][2]);
            acc[j][3] = fmaf(a[j], w4.w, acc[j][3]);
        }
    }
#pragma unroll
    for (int j = 0; j < 8; j++) {
        int gn = n0 + tn + j;
        if (gn < Nn) {
            float4 p = *(const float4*)(prev + (size_t)gn * 64 + tf);
            float4 r;
            r.x = p.x + fmaxf(acc[j][0], 0.f);
            r.y = p.y + fmaxf(acc[j][1], 0.f);
            r.z = p.z + fmaxf(acc[j][2], 0.f);
            r.w = p.w + fmaxf(acc[j][3], 0.f);
            *(float4*)(out + (size_t)gn * 64 + tf) = r;
        }
    }
}

// ---------------------------------------------------------------------------
extern "C" void kernel_launch(void* const* d_in, const int* in_sizes, int n_in,
                              void* d_out, int out_size) {
    const float* x  = (const float*)d_in[0];
    const int*   ei = (const int*)d_in[1];   // int32 (harness: int64 -> int32)
    const float* ew = (const float*)d_in[2];
    // d_in[3] = edge_attr (unused by the module)
    const float* w0 = (const float*)d_in[4];
    const float* b0 = (const float*)d_in[5];
    const float* w1 = (const float*)d_in[6];
    float* out = (float*)d_out;

    const int* rows = ei;
    const int* cols = ei + Ee;

    const int EB = (Ee + 255) / 256;
    const int NB = (Nn + 255) / 256;
    const int GB = (Nn + 127) / 128;       // gemm blocks (128 nodes/block)
    const int WB = (Nn + 7) / 8;           // gather blocks (8 warps/block)

    zero_kernel<<<NB, 256>>>();
    deg_kernel<<<EB, 256>>>(cols, ew);
    dinv_kernel<<<NB, 256>>>();
    scan_sum_kernel<<<SCAN_B, 1024>>>();
    scan_base_kernel<<<1, 128>>>();
    scan_final_kernel<<<SCAN_B, 1024>>>();
    scatter_kernel<<<EB, 256>>>(rows, cols, ew);
    gemm_h0_kernel<<<GB, 256>>>(x, w0, b0);

    // layer 1
    gather_kernel<<<WB, 256>>>(0);
    gemm_conv_kernel<<<GB, 256>>>(w1, 0, out);

    // layer 2
    gather_kernel<<<WB, 256>>>(1);
    gemm_conv_kernel<<<GB, 256>>>(w1 + 64 * 64, 1, out);
}

// round 6
// speedup vs baseline: 1.5547x; 1.0134x over previous
#include <cuda_runtime.h>

#define Nn 100000
#define Ff 64
#define Ee 1600000
#define SCAN_B 98   // ceil(Nn/1024)

// Scratch (device globals — no allocation allowed anywhere)
__device__ float g_deg[Nn];
__device__ float g_dinv[Nn];
__device__ int   g_cnt[Nn];
__device__ int   g_off[Nn];
__device__ int   g_cursor[Nn];
__device__ int   g_bsum[128];
__device__ int   g_bbase[128];
__device__ int2  g_csr[Ee];          // (row, __float_as_int(nw))
__device__ float g_h0[(size_t)Nn * Ff];
__device__ float g_agg[(size_t)Nn * Ff];
__device__ float g_out1[(size_t)Nn * Ff];

// ---------------------------------------------------------------------------
__global__ void zero_kernel() {
    int i = blockIdx.x * blockDim.x + threadIdx.x;
    if (i < Nn) { g_deg[i] = 0.f; g_cnt[i] = 0; }
}

// ---------------------------------------------------------------------------
// deg[col[e]] += w[e];  cnt[col[e]] += 1
// ---------------------------------------------------------------------------
__global__ void deg_kernel(const int* __restrict__ cols,
                           const float* __restrict__ ew) {
    int e = blockIdx.x * blockDim.x + threadIdx.x;
    if (e < Ee) {
        unsigned c = (unsigned)cols[e];
        if (c < Nn) {
            atomicAdd(&g_deg[c], ew[e]);
            atomicAdd(&g_cnt[c], 1);
        }
    }
}

__global__ void dinv_kernel() {
    int i = blockIdx.x * blockDim.x + threadIdx.x;
    if (i < Nn) {
        float d = g_deg[i];
        g_dinv[i] = d > 0.f ? rsqrtf(d) : 0.f;
    }
}

// ---------------------------------------------------------------------------
// 3-phase exclusive scan of g_cnt -> g_off/g_cursor
// ---------------------------------------------------------------------------
__global__ void __launch_bounds__(1024)
scan_sum_kernel() {
    __shared__ int sm[1024];
    int t = threadIdx.x;
    int i = blockIdx.x * 1024 + t;
    sm[t] = (i < Nn) ? g_cnt[i] : 0;
    __syncthreads();
    for (int d = 512; d > 0; d >>= 1) {
        if (t < d) sm[t] += sm[t + d];
        __syncthreads();
    }
    if (t == 0) g_bsum[blockIdx.x] = sm[0];
}

__global__ void __launch_bounds__(128)
scan_base_kernel() {
    __shared__ int sm[128];
    int t = threadIdx.x;
    int v = (t < SCAN_B) ? g_bsum[t] : 0;
    sm[t] = v;
    __syncthreads();
    for (int d = 1; d < 128; d <<= 1) {
        int u = (t >= d) ? sm[t - d] : 0;
        __syncthreads();
        sm[t] += u;
        __syncthreads();
    }
    if (t < SCAN_B) g_bbase[t] = sm[t] - v;  // exclusive
}

__global__ void __launch_bounds__(1024)
scan_final_kernel() {
    __shared__ int sm[1024];
    int t = threadIdx.x;
    int i = blockIdx.x * 1024 + t;
    int v = (i < Nn) ? g_cnt[i] : 0;
    sm[t] = v;
    __syncthreads();
    for (int d = 1; d < 1024; d <<= 1) {
        int u = (t >= d) ? sm[t - d] : 0;
        __syncthreads();
        sm[t] += u;
        __syncthreads();
    }
    if (i < Nn) {
        int off = g_bbase[blockIdx.x] + sm[t] - v;
        g_off[i] = off;
        g_cursor[i] = off;
    }
}

// ---------------------------------------------------------------------------
// Scatter edges into packed CSR slots (one 8B write per edge).
// ---------------------------------------------------------------------------
__global__ void scatter_kernel(const int* __restrict__ rows,
                               const int* __restrict__ cols,
                               const float* __restrict__ ew) {
    int e = blockIdx.x * blockDim.x + threadIdx.x;
    if (e < Ee) {
        unsigned r = (unsigned)rows[e];
        unsigned c = (unsigned)cols[e];
        if (r < Nn && c < Nn) {
            int p = atomicAdd(&g_cursor[c], 1);
            float nw = g_dinv[r] * ew[e] * g_dinv[c];
            g_csr[p] = make_int2((int)r, __float_as_int(nw));
        }
    }
}

// ---------------------------------------------------------------------------
// SpMM gather: agg[n] = sum_{edges into n} nw * h[row].  One warp per node,
// each lane owns 2 feature floats. 4 independent streams for MLP.
// ---------------------------------------------------------------------------
__global__ void __launch_bounds__(256)
gather_kernel(int src) {
    int w = (blockIdx.x * 256 + threadIdx.x) >> 5;   // node id
    int lane = threadIdx.x & 31;
    if (w >= Nn) return;
    const float* __restrict__ h = src ? g_out1 : g_h0;
    int beg = g_off[w];
    int end = beg + g_cnt[w];
    float2 a0 = make_float2(0.f, 0.f);
    float2 a1 = make_float2(0.f, 0.f);
    float2 a2 = make_float2(0.f, 0.f);
    float2 a3 = make_float2(0.f, 0.f);
    int j = beg;
    for (; j + 4 <= end; j += 4) {
        int2 c0 = g_csr[j];
        int2 c1 = g_csr[j + 1];
        int2 c2 = g_csr[j + 2];
        int2 c3 = g_csr[j + 3];
        float2 v0 = *(const float2*)(h + (size_t)c0.x * Ff + lane * 2);
        float2 v1 = *(const float2*)(h + (size_t)c1.x * Ff + lane * 2);
        float2 v2 = *(const float2*)(h + (size_t)c2.x * Ff + lane * 2);
        float2 v3 = *(const float2*)(h + (size_t)c3.x * Ff + lane * 2);
        float w0 = __int_as_float(c0.y), w1 = __int_as_float(c1.y);
        float w2 = __int_as_float(c2.y), w3 = __int_as_float(c3.y);
        a0.x = fmaf(w0, v0.x, a0.x); a0.y = fmaf(w0, v0.y, a0.y);
        a1.x = fmaf(w1, v1.x, a1.x); a1.y = fmaf(w1, v1.y, a1.y);
        a2.x = fmaf(w2, v2.x, a2.x); a2.y = fmaf(w2, v2.y, a2.y);
        a3.x = fmaf(w3, v3.x, a3.x); a3.y = fmaf(w3, v3.y, a3.y);
    }
    for (; j < end; j++) {
        int2 c0 = g_csr[j];
        float2 v0 = *(const float2*)(h + (size_t)c0.x * Ff + lane * 2);
        float w0 = __int_as_float(c0.y);
        a0.x = fmaf(w0, v0.x, a0.x); a0.y = fmaf(w0, v0.y, a0.y);
    }
    a0.x += a1.x + a2.x + a3.x;
    a0.y += a1.y + a2.y + a3.y;
    *(float2*)(g_agg + (size_t)w * Ff + lane * 2) = a0;
}

// ---------------------------------------------------------------------------
// GEMM h0 = relu(x @ W0^T + b).  Block tile: 128 nodes x 64 feats, 256 thr.
// ---------------------------------------------------------------------------
__global__ void __launch_bounds__(256)
gemm_h0_kernel(const float* __restrict__ x, const float* __restrict__ w0,
               const float* __restrict__ b) {
    __shared__ __align__(16) float As[64][128];  // [k][node]
    __shared__ __align__(16) float Ws[64][64];   // [k][f]
    int t = threadIdx.x;
    int n0 = blockIdx.x * 128;

    for (int i = t; i < 4096; i += 256) {
        int k = i >> 6, f = i & 63;
        Ws[k][f] = w0[f * 64 + k];  // transpose: need W0[f][k] at [k][f]
    }
    for (int i = t * 4; i < 8192; i += 1024) {
        int node = i >> 6, k = i & 63;
        int gn = n0 + node;
        float4 v = make_float4(0.f, 0.f, 0.f, 0.f);
        if (gn < Nn) v = *(const float4*)(x + (size_t)gn * 64 + k);
        As[k + 0][node] = v.x; As[k + 1][node] = v.y;
        As[k + 2][node] = v.z; As[k + 3][node] = v.w;
    }
    __syncthreads();

    int tf = (t & 15) * 4;
    int tn = (t >> 4) * 8;
    float acc[8][4];
#pragma unroll
    for (int j = 0; j < 8; j++)
        acc[j][0] = acc[j][1] = acc[j][2] = acc[j][3] = 0.f;

#pragma unroll 8
    for (int k = 0; k < 64; k++) {
        float4 w4 = *(const float4*)&Ws[k][tf];
        float4 b0v = *(const float4*)&As[k][tn];
        float4 b1v = *(const float4*)&As[k][tn + 4];
        float a[8] = {b0v.x, b0v.y, b0v.z, b0v.w, b1v.x, b1v.y, b1v.z, b1v.w};
#pragma unroll
        for (int j = 0; j < 8; j++) {
            acc[j][0] = fmaf(a[j], w4.x, acc[j][0]);
            acc[j][1] = fmaf(a[j], w4.y, acc[j][1]);
            acc[j][2] = fmaf(a[j], w4.z, acc[j][2]);
            acc[j][3] = fmaf(a[j], w4.w, acc[j][3]);
        }
    }
    float4 bv = *(const float4*)(b + tf);
#pragma unroll
    for (int j = 0; j < 8; j++) {
        int gn = n0 + tn + j;
        if (gn < Nn) {
            float4 r;
            r.x = fmaxf(acc[j][0] + bv.x, 0.f);
            r.y = fmaxf(acc[j][1] + bv.y, 0.f);
            r.z = fmaxf(acc[j][2] + bv.z, 0.f);
            r.w = fmaxf(acc[j][3] + bv.w, 0.f);
            *(float4*)&g_h0[(size_t)gn * 64 + tf] = r;
        }
    }
}

// ---------------------------------------------------------------------------
// Fused conv GEMM: out = prev + relu( (0.1*agg + 0.9*h0) @ W1 )
// ---------------------------------------------------------------------------
__global__ void __launch_bounds__(256)
gemm_conv_kernel(const float* __restrict__ w1, int layer,
                 float* __restrict__ dout) {
    __shared__ __align__(16) float As[64][128];
    __shared__ __align__(16) float Ws[64][64];
    int t = threadIdx.x;
    int n0 = blockIdx.x * 128;
    const float* __restrict__ prev = layer ? g_out1 : g_h0;
    float* __restrict__ out = layer ? dout : g_out1;

    for (int i = t; i < 4096; i += 256) {
        Ws[i >> 6][i & 63] = w1[i];  // already [k][f]
    }
    for (int i = t * 4; i < 8192; i += 1024) {
        int node = i >> 6, k = i & 63;
        int gn = n0 + node;
        float4 v = make_float4(0.f, 0.f, 0.f, 0.f);
        if (gn < Nn) {
            float4 a = *(const float4*)(g_agg + (size_t)gn * 64 + k);
            float4 h = *(const float4*)(g_h0 + (size_t)gn * 64 + k);
            v.x = fmaf(0.1f, a.x, 0.9f * h.x);
            v.y = fmaf(0.1f, a.y, 0.9f * h.y);
            v.z = fmaf(0.1f, a.z, 0.9f * h.z);
            v.w = fmaf(0.1f, a.w, 0.9f * h.w);
        }
        As[k + 0][node] = v.x; As[k + 1][node] = v.y;
        As[k + 2][node] = v.z; As[k + 3][node] = v.w;
    }
    __syncthreads();

    int tf = (t & 15) * 4;
    int tn = (t >> 4) * 8;
    float acc[8][4];
#pragma unroll
    for (int j = 0; j < 8; j++)
        acc[j][0] = acc[j][1] = acc[j][2] = acc[j][3] = 0.f;

#pragma unroll 8
    for (int k = 0; k < 64; k++) {
        float4 w4 = *(const float4*)&Ws[k][tf];
        float4 b0v = *(const float4*)&As[k][tn];
        float4 b1v = *(const float4*)&As[k][tn + 4];
        float a[8] = {b0v.x, b0v.y, b0v.z, b0v.w, b1v.x, b1v.y, b1v.z, b1v.w};
#pragma unroll
        for (int j = 0; j < 8; j++) {
            acc[j][0] = fmaf(a[j], w4.x, acc[j][0]);
            acc[j][1] = fmaf(a[j], w4.y, acc[j][1]);
            acc[j][2] = fmaf(a[j], w4.z, acc[j][2]);
            acc[j][3] = fmaf(a[j], w4.w, acc[j][3]);
        }
    }
#pragma unroll
    for (int j = 0; j < 8; j++) {
        int gn = n0 + tn + j;
        if (gn < Nn) {
            float4 p = *(const float4*)(prev + (size_t)gn * 64 + tf);
            float4 r;
            r.x = p.x + fmaxf(acc[j][0], 0.f);
            r.y = p.y + fmaxf(acc[j][1], 0.f);
            r.z = p.z + fmaxf(acc[j][2], 0.f);
            r.w = p.w + fmaxf(acc[j][3], 0.f);
            *(float4*)(out + (size_t)gn * 64 + tf) = r;
        }
    }
}

// ---------------------------------------------------------------------------
extern "C" void kernel_launch(void* const* d_in, const int* in_sizes, int n_in,
                              void* d_out, int out_size) {
    const float* x  = (const float*)d_in[0];
    const int*   ei = (const int*)d_in[1];   // int32 (harness: int64 -> int32)
    const float* ew = (const float*)d_in[2];
    // d_in[3] = edge_attr (unused by the module)
    const float* w0 = (const float*)d_in[4];
    const float* b0 = (const float*)d_in[5];
    const float* w1 = (const float*)d_in[6];
    float* out = (float*)d_out;

    const int* rows = ei;
    const int* cols = ei + Ee;

    const int EB = (Ee + 255) / 256;
    const int NB = (Nn + 255) / 256;
    const int GB = (Nn + 127) / 128;
    const int WB = (Nn + 7) / 8;

    // Lazily created side stream + events (created on the first, uncaptured,
    // correctness call; only recorded/waited during capture — the documented
    // multi-stream graph fork/join pattern).
    static cudaStream_t s1 = nullptr;
    static cudaEvent_t ev_fork = nullptr, ev_join = nullptr;
    if (s1 == nullptr) {
        cudaStreamCreateWithFlags(&s1, cudaStreamNonBlocking);
        cudaEventCreateWithFlags(&ev_fork, cudaEventDisableTiming);
        cudaEventCreateWithFlags(&ev_join, cudaEventDisableTiming);
    }

    // Fork: gemm_h0 is independent of the CSR build chain.
    cudaEventRecord(ev_fork, 0);
    cudaStreamWaitEvent(s1, ev_fork, 0);
    gemm_h0_kernel<<<GB, 256, 0, s1>>>(x, w0, b0);
    cudaEventRecord(ev_join, s1);

    // CSR build chain on the main stream.
    zero_kernel<<<NB, 256>>>();
    deg_kernel<<<EB, 256>>>(cols, ew);
    dinv_kernel<<<NB, 256>>>();
    scan_sum_kernel<<<SCAN_B, 1024>>>();
    scan_base_kernel<<<1, 128>>>();
    scan_final_kernel<<<SCAN_B, 1024>>>();
    scatter_kernel<<<EB, 256>>>(rows, cols, ew);

    // Join: gather needs both h0 and the CSR.
    cudaStreamWaitEvent(0, ev_join, 0);

    // layer 1
    gather_kernel<<<WB, 256>>>(0);
    gemm_conv_kernel<<<GB, 256>>>(w1, 0, out);

    // layer 2
    gather_kernel<<<WB, 256>>>(1);
    gemm_conv_kernel<<<GB, 256>>>(w1 + 64 * 64, 1, out);
}

// round 7
// speedup vs baseline: 1.6523x; 1.0628x over previous
#include <cuda_runtime.h>
#include <cuda_fp16.h>

#define Nn 100000
#define Ff 64
#define Ee 1600000
#define SCAN_B 98   // ceil(Nn/1024)

// Scratch (device globals — no allocation allowed anywhere)
__device__ float  g_deg[Nn];
__device__ float  g_dinv[Nn];
__device__ int    g_cnt[Nn];
__device__ int    g_off[Nn];
__device__ int    g_cursor[Nn];
__device__ int    g_bsum[128];
__device__ int    g_bbase[128];
__device__ int2   g_csr[Ee];          // (row, __float_as_int(nw))
__device__ float  g_h0[(size_t)Nn * Ff];
__device__ float  g_agg[(size_t)Nn * Ff];
__device__ float  g_out1[(size_t)Nn * Ff];
__device__ __half g_h16[(size_t)Nn * Ff];   // fp16 shadow of h0   (gather src)
__device__ __half g_o16[(size_t)Nn * Ff];   // fp16 shadow of out1 (gather src)

// ---------------------------------------------------------------------------
__global__ void zero_kernel() {
    int i = blockIdx.x * blockDim.x + threadIdx.x;
    if (i < Nn) { g_deg[i] = 0.f; g_cnt[i] = 0; }
}

// ---------------------------------------------------------------------------
// deg[col[e]] += w[e];  cnt[col[e]] += 1
// ---------------------------------------------------------------------------
__global__ void deg_kernel(const int* __restrict__ cols,
                           const float* __restrict__ ew) {
    int e = blockIdx.x * blockDim.x + threadIdx.x;
    if (e < Ee) {
        unsigned c = (unsigned)cols[e];
        if (c < Nn) {
            atomicAdd(&g_deg[c], ew[e]);
            atomicAdd(&g_cnt[c], 1);
        }
    }
}

__global__ void dinv_kernel() {
    int i = blockIdx.x * blockDim.x + threadIdx.x;
    if (i < Nn) {
        float d = g_deg[i];
        g_dinv[i] = d > 0.f ? rsqrtf(d) : 0.f;
    }
}

// ---------------------------------------------------------------------------
// 3-phase exclusive scan of g_cnt -> g_off/g_cursor
// ---------------------------------------------------------------------------
__global__ void __launch_bounds__(1024)
scan_sum_kernel() {
    __shared__ int sm[1024];
    int t = threadIdx.x;
    int i = blockIdx.x * 1024 + t;
    sm[t] = (i < Nn) ? g_cnt[i] : 0;
    __syncthreads();
    for (int d = 512; d > 0; d >>= 1) {
        if (t < d) sm[t] += sm[t + d];
        __syncthreads();
    }
    if (t == 0) g_bsum[blockIdx.x] = sm[0];
}

__global__ void __launch_bounds__(128)
scan_base_kernel() {
    __shared__ int sm[128];
    int t = threadIdx.x;
    int v = (t < SCAN_B) ? g_bsum[t] : 0;
    sm[t] = v;
    __syncthreads();
    for (int d = 1; d < 128; d <<= 1) {
        int u = (t >= d) ? sm[t - d] : 0;
        __syncthreads();
        sm[t] += u;
        __syncthreads();
    }
    if (t < SCAN_B) g_bbase[t] = sm[t] - v;  // exclusive
}

__global__ void __launch_bounds__(1024)
scan_final_kernel() {
    __shared__ int sm[1024];
    int t = threadIdx.x;
    int i = blockIdx.x * 1024 + t;
    int v = (i < Nn) ? g_cnt[i] : 0;
    sm[t] = v;
    __syncthreads();
    for (int d = 1; d < 1024; d <<= 1) {
        int u = (t >= d) ? sm[t - d] : 0;
        __syncthreads();
        sm[t] += u;
        __syncthreads();
    }
    if (i < Nn) {
        int off = g_bbase[blockIdx.x] + sm[t] - v;
        g_off[i] = off;
        g_cursor[i] = off;
    }
}

// ---------------------------------------------------------------------------
// Scatter edges into packed CSR slots (one 8B write per edge).
// ---------------------------------------------------------------------------
__global__ void scatter_kernel(const int* __restrict__ rows,
                               const int* __restrict__ cols,
                               const float* __restrict__ ew) {
    int e = blockIdx.x * blockDim.x + threadIdx.x;
    if (e < Ee) {
        unsigned r = (unsigned)rows[e];
        unsigned c = (unsigned)cols[e];
        if (r < Nn && c < Nn) {
            int p = atomicAdd(&g_cursor[c], 1);
            float nw = g_dinv[r] * ew[e] * g_dinv[c];
            g_csr[p] = make_int2((int)r, __float_as_int(nw));
        }
    }
}

// ---------------------------------------------------------------------------
// SpMM gather (fp16 source): agg[n] = sum nw * h16[row].  One warp per node,
// lane owns 2 feats (one __half2 = 4B -> 128B per edge-row, one L2 line).
// ---------------------------------------------------------------------------
__global__ void __launch_bounds__(256)
gather_kernel(int src) {
    int w = (blockIdx.x * 256 + threadIdx.x) >> 5;   // node id
    int lane = threadIdx.x & 31;
    if (w >= Nn) return;
    const __half* __restrict__ h = src ? g_o16 : g_h16;
    int beg = g_off[w];
    int end = beg + g_cnt[w];
    float2 a0 = make_float2(0.f, 0.f);
    float2 a1 = make_float2(0.f, 0.f);
    float2 a2 = make_float2(0.f, 0.f);
    float2 a3 = make_float2(0.f, 0.f);
    int j = beg;
    for (; j + 4 <= end; j += 4) {
        int2 c0 = g_csr[j];
        int2 c1 = g_csr[j + 1];
        int2 c2 = g_csr[j + 2];
        int2 c3 = g_csr[j + 3];
        float2 v0 = __half22float2(*(const __half2*)(h + (size_t)c0.x * Ff + lane * 2));
        float2 v1 = __half22float2(*(const __half2*)(h + (size_t)c1.x * Ff + lane * 2));
        float2 v2 = __half22float2(*(const __half2*)(h + (size_t)c2.x * Ff + lane * 2));
        float2 v3 = __half22float2(*(const __half2*)(h + (size_t)c3.x * Ff + lane * 2));
        float w0 = __int_as_float(c0.y), w1 = __int_as_float(c1.y);
        float w2 = __int_as_float(c2.y), w3 = __int_as_float(c3.y);
        a0.x = fmaf(w0, v0.x, a0.x); a0.y = fmaf(w0, v0.y, a0.y);
        a1.x = fmaf(w1, v1.x, a1.x); a1.y = fmaf(w1, v1.y, a1.y);
        a2.x = fmaf(w2, v2.x, a2.x); a2.y = fmaf(w2, v2.y, a2.y);
        a3.x = fmaf(w3, v3.x, a3.x); a3.y = fmaf(w3, v3.y, a3.y);
    }
    for (; j < end; j++) {
        int2 c0 = g_csr[j];
        float2 v0 = __half22float2(*(const __half2*)(h + (size_t)c0.x * Ff + lane * 2));
        float w0 = __int_as_float(c0.y);
        a0.x = fmaf(w0, v0.x, a0.x); a0.y = fmaf(w0, v0.y, a0.y);
    }
    a0.x += a1.x + a2.x + a3.x;
    a0.y += a1.y + a2.y + a3.y;
    *(float2*)(g_agg + (size_t)w * Ff + lane * 2) = a0;
}

// ---------------------------------------------------------------------------
// GEMM h0 = relu(x @ W0^T + b).  Also writes fp16 shadow for the gather.
// ---------------------------------------------------------------------------
__global__ void __launch_bounds__(256)
gemm_h0_kernel(const float* __restrict__ x, const float* __restrict__ w0,
               const float* __restrict__ b) {
    __shared__ __align__(16) float As[64][128];  // [k][node]
    __shared__ __align__(16) float Ws[64][64];   // [k][f]
    int t = threadIdx.x;
    int n0 = blockIdx.x * 128;

    for (int i = t; i < 4096; i += 256) {
        int k = i >> 6, f = i & 63;
        Ws[k][f] = w0[f * 64 + k];  // transpose: need W0[f][k] at [k][f]
    }
    for (int i = t * 4; i < 8192; i += 1024) {
        int node = i >> 6, k = i & 63;
        int gn = n0 + node;
        float4 v = make_float4(0.f, 0.f, 0.f, 0.f);
        if (gn < Nn) v = *(const float4*)(x + (size_t)gn * 64 + k);
        As[k + 0][node] = v.x; As[k + 1][node] = v.y;
        As[k + 2][node] = v.z; As[k + 3][node] = v.w;
    }
    __syncthreads();

    int tf = (t & 15) * 4;
    int tn = (t >> 4) * 8;
    float acc[8][4];
#pragma unroll
    for (int j = 0; j < 8; j++)
        acc[j][0] = acc[j][1] = acc[j][2] = acc[j][3] = 0.f;

#pragma unroll 8
    for (int k = 0; k < 64; k++) {
        float4 w4 = *(const float4*)&Ws[k][tf];
        float4 b0v = *(const float4*)&As[k][tn];
        float4 b1v = *(const float4*)&As[k][tn + 4];
        float a[8] = {b0v.x, b0v.y, b0v.z, b0v.w, b1v.x, b1v.y, b1v.z, b1v.w};
#pragma unroll
        for (int j = 0; j < 8; j++) {
            acc[j][0] = fmaf(a[j], w4.x, acc[j][0]);
            acc[j][1] = fmaf(a[j], w4.y, acc[j][1]);
            acc[j][2] = fmaf(a[j], w4.z, acc[j][2]);
            acc[j][3] = fmaf(a[j], w4.w, acc[j][3]);
        }
    }
    float4 bv = *(const float4*)(b + tf);
#pragma unroll
    for (int j = 0; j < 8; j++) {
        int gn = n0 + tn + j;
        if (gn < Nn) {
            float4 r;
            r.x = fmaxf(acc[j][0] + bv.x, 0.f);
            r.y = fmaxf(acc[j][1] + bv.y, 0.f);
            r.z = fmaxf(acc[j][2] + bv.z, 0.f);
            r.w = fmaxf(acc[j][3] + bv.w, 0.f);
            *(float4*)&g_h0[(size_t)gn * 64 + tf] = r;
            __half2 p0 = __floats2half2_rn(r.x, r.y);
            __half2 p1 = __floats2half2_rn(r.z, r.w);
            *(__half2*)&g_h16[(size_t)gn * 64 + tf] = p0;
            *(__half2*)&g_h16[(size_t)gn * 64 + tf + 2] = p1;
        }
    }
}

// ---------------------------------------------------------------------------
// Fused conv GEMM: out = prev + relu( (0.1*agg + 0.9*h0) @ W1 )
// layer 0 also writes the fp16 shadow of out1 for the layer-2 gather.
// ---------------------------------------------------------------------------
__global__ void __launch_bounds__(256)
gemm_conv_kernel(const float* __restrict__ w1, int layer,
                 float* __restrict__ dout) {
    __shared__ __align__(16) float As[64][128];
    __shared__ __align__(16) float Ws[64][64];
    int t = threadIdx.x;
    int n0 = blockIdx.x * 128;
    const float* __restrict__ prev = layer ? g_out1 : g_h0;
    float* __restrict__ out = layer ? dout : g_out1;

    for (int i = t; i < 4096; i += 256) {
        Ws[i >> 6][i & 63] = w1[i];  // already [k][f]
    }
    for (int i = t * 4; i < 8192; i += 1024) {
        int node = i >> 6, k = i & 63;
        int gn = n0 + node;
        float4 v = make_float4(0.f, 0.f, 0.f, 0.f);
        if (gn < Nn) {
            float4 a = *(const float4*)(g_agg + (size_t)gn * 64 + k);
            float4 h = *(const float4*)(g_h0 + (size_t)gn * 64 + k);
            v.x = fmaf(0.1f, a.x, 0.9f * h.x);
            v.y = fmaf(0.1f, a.y, 0.9f * h.y);
            v.z = fmaf(0.1f, a.z, 0.9f * h.z);
            v.w = fmaf(0.1f, a.w, 0.9f * h.w);
        }
        As[k + 0][node] = v.x; As[k + 1][node] = v.y;
        As[k + 2][node] = v.z; As[k + 3][node] = v.w;
    }
    __syncthreads();

    int tf = (t & 15) * 4;
    int tn = (t >> 4) * 8;
    float acc[8][4];
#pragma unroll
    for (int j = 0; j < 8; j++)
        acc[j][0] = acc[j][1] = acc[j][2] = acc[j][3] = 0.f;

#pragma unroll 8
    for (int k = 0; k < 64; k++) {
        float4 w4 = *(const float4*)&Ws[k][tf];
        float4 b0v = *(const float4*)&As[k][tn];
        float4 b1v = *(const float4*)&As[k][tn + 4];
        float a[8] = {b0v.x, b0v.y, b0v.z, b0v.w, b1v.x, b1v.y, b1v.z, b1v.w};
#pragma unroll
        for (int j = 0; j < 8; j++) {
            acc[j][0] = fmaf(a[j], w4.x, acc[j][0]);
            acc[j][1] = fmaf(a[j], w4.y, acc[j][1]);
            acc[j][2] = fmaf(a[j], w4.z, acc[j][2]);
            acc[j][3] = fmaf(a[j], w4.w, acc[j][3]);
        }
    }
#pragma unroll
    for (int j = 0; j < 8; j++) {
        int gn = n0 + tn + j;
        if (gn < Nn) {
            float4 p = *(const float4*)(prev + (size_t)gn * 64 + tf);
            float4 r;
            r.x = p.x + fmaxf(acc[j][0], 0.f);
            r.y = p.y + fmaxf(acc[j][1], 0.f);
            r.z = p.z + fmaxf(acc[j][2], 0.f);
            r.w = p.w + fmaxf(acc[j][3], 0.f);
            *(float4*)(out + (size_t)gn * 64 + tf) = r;
            if (layer == 0) {
                __half2 p0 = __floats2half2_rn(r.x, r.y);
                __half2 p1 = __floats2half2_rn(r.z, r.w);
                *(__half2*)&g_o16[(size_t)gn * 64 + tf] = p0;
                *(__half2*)&g_o16[(size_t)gn * 64 + tf + 2] = p1;
            }
        }
    }
}

// ---------------------------------------------------------------------------
extern "C" void kernel_launch(void* const* d_in, const int* in_sizes, int n_in,
                              void* d_out, int out_size) {
    const float* x  = (const float*)d_in[0];
    const int*   ei = (const int*)d_in[1];   // int32 (harness: int64 -> int32)
    const float* ew = (const float*)d_in[2];
    // d_in[3] = edge_attr (unused by the module)
    const float* w0 = (const float*)d_in[4];
    const float* b0 = (const float*)d_in[5];
    const float* w1 = (const float*)d_in[6];
    float* out = (float*)d_out;

    const int* rows = ei;
    const int* cols = ei + Ee;

    const int EB = (Ee + 255) / 256;
    const int NB = (Nn + 255) / 256;
    const int GB = (Nn + 127) / 128;
    const int WB = (Nn + 7) / 8;

    static cudaStream_t s1 = nullptr;
    static cudaEvent_t ev_fork = nullptr, ev_join = nullptr;
    if (s1 == nullptr) {
        cudaStreamCreateWithFlags(&s1, cudaStreamNonBlocking);
        cudaEventCreateWithFlags(&ev_fork, cudaEventDisableTiming);
        cudaEventCreateWithFlags(&ev_join, cudaEventDisableTiming);
    }

    // Fork: gemm_h0 is independent of the CSR build chain.
    cudaEventRecord(ev_fork, 0);
    cudaStreamWaitEvent(s1, ev_fork, 0);
    gemm_h0_kernel<<<GB, 256, 0, s1>>>(x, w0, b0);
    cudaEventRecord(ev_join, s1);

    // CSR build chain on the main stream.
    zero_kernel<<<NB, 256>>>();
    deg_kernel<<<EB, 256>>>(cols, ew);
    dinv_kernel<<<NB, 256>>>();
    scan_sum_kernel<<<SCAN_B, 1024>>>();
    scan_base_kernel<<<1, 128>>>();
    scan_final_kernel<<<SCAN_B, 1024>>>();
    scatter_kernel<<<EB, 256>>>(rows, cols, ew);

    // Join: gather needs both h0 and the CSR.
    cudaStreamWaitEvent(0, ev_join, 0);

    // layer 1
    gather_kernel<<<WB, 256>>>(0);
    gemm_conv_kernel<<<GB, 256>>>(w1, 0, out);

    // layer 2
    gather_kernel<<<WB, 256>>>(1);
    gemm_conv_kernel<<<GB, 256>>>(w1 + 64 * 64, 1, out);
}